// round 5
// baseline (speedup 1.0000x reference)
#include <cuda_runtime.h>
#include <cuda_bf16.h>
#include <cstdint>
#include <cstddef>

// Problem dims (fixed by the dataset)
#define BATCH   8192
#define NREG    14
#define DDIM    768
#define M_TOTAL (BATCH * NREG)   // 114688 = 128 * 896
#define K_DIM   768              // 32 * 24
#define N_DIM   768              // 128 * 6

// ---------------------------------------------------------------------------
// Device scratch (allocation-free rule: __device__ globals)
// ---------------------------------------------------------------------------
__device__ __nv_bfloat16 g_Abf[(size_t)M_TOTAL * K_DIM];   // X in bf16
__device__ __nv_bfloat16 g_Wbf[(size_t)K_DIM * N_DIM];     // W in bf16
__device__ __nv_bfloat16 g_feats[(size_t)M_TOTAL * N_DIM]; // X@W + b in bf16

// ---------------------------------------------------------------------------
// fp32 -> bf16 converters (8 elems / thread, fully vectorized)
// ---------------------------------------------------------------------------
__global__ __launch_bounds__(256) void cvtA_kernel(const float* __restrict__ src) {
    size_t i = ((size_t)blockIdx.x * 256 + threadIdx.x) * 8;
    float4 v0 = *(const float4*)(src + i);
    float4 v1 = *(const float4*)(src + i + 4);
    union { __nv_bfloat162 h[4]; uint4 u; } pk;
    pk.h[0] = __floats2bfloat162_rn(v0.x, v0.y);
    pk.h[1] = __floats2bfloat162_rn(v0.z, v0.w);
    pk.h[2] = __floats2bfloat162_rn(v1.x, v1.y);
    pk.h[3] = __floats2bfloat162_rn(v1.z, v1.w);
    *(uint4*)(g_Abf + i) = pk.u;
}

__global__ __launch_bounds__(256) void cvtW_kernel(const float* __restrict__ src) {
    size_t i = ((size_t)blockIdx.x * 256 + threadIdx.x) * 8;
    float4 v0 = *(const float4*)(src + i);
    float4 v1 = *(const float4*)(src + i + 4);
    union { __nv_bfloat162 h[4]; uint4 u; } pk;
    pk.h[0] = __floats2bfloat162_rn(v0.x, v0.y);
    pk.h[1] = __floats2bfloat162_rn(v0.z, v0.w);
    pk.h[2] = __floats2bfloat162_rn(v1.x, v1.y);
    pk.h[3] = __floats2bfloat162_rn(v1.z, v1.w);
    *(uint4*)(g_Wbf + i) = pk.u;
}

// ---------------------------------------------------------------------------
// bf16 tensor-core GEMM: feats[M,768] = Abf[M,768] @ Wbf[768,768] + bias
// BM=128, BN=128, BK=32, 256 threads (8 warps, warp tile 32x64), 3-stage
// cp.async pipeline, xor-swizzled smem for conflict-free ldmatrix.
// ---------------------------------------------------------------------------
__device__ __forceinline__ void cp_async16(uint32_t smem, const void* g) {
    asm volatile("cp.async.cg.shared.global [%0], [%1], 16;\n" :: "r"(smem), "l"(g));
}
__device__ __forceinline__ void ldm_x4(uint32_t& r0, uint32_t& r1, uint32_t& r2, uint32_t& r3,
                                       uint32_t addr) {
    asm volatile("ldmatrix.sync.aligned.m8n8.x4.shared.b16 {%0,%1,%2,%3}, [%4];"
                 : "=r"(r0), "=r"(r1), "=r"(r2), "=r"(r3) : "r"(addr));
}
__device__ __forceinline__ void ldm_x4_t(uint32_t& r0, uint32_t& r1, uint32_t& r2, uint32_t& r3,
                                         uint32_t addr) {
    asm volatile("ldmatrix.sync.aligned.m8n8.x4.trans.shared.b16 {%0,%1,%2,%3}, [%4];"
                 : "=r"(r0), "=r"(r1), "=r"(r2), "=r"(r3) : "r"(addr));
}
__device__ __forceinline__ void mma_bf16(float* d, const uint32_t* a, uint32_t b0, uint32_t b1) {
    asm volatile("mma.sync.aligned.m16n8k16.row.col.f32.bf16.bf16.f32 "
                 "{%0,%1,%2,%3}, {%4,%5,%6,%7}, {%8,%9}, {%0,%1,%2,%3};"
                 : "+f"(d[0]), "+f"(d[1]), "+f"(d[2]), "+f"(d[3])
                 : "r"(a[0]), "r"(a[1]), "r"(a[2]), "r"(a[3]), "r"(b0), "r"(b1));
}

#define KTILES 24
#define STAGES 3

__global__ __launch_bounds__(256, 2) void gemm_kernel(const float* __restrict__ bias) {
    __shared__ __nv_bfloat16 sA[STAGES][128 * 32];   // 24 KB
    __shared__ __nv_bfloat16 sB[STAGES][32 * 128];   // 24 KB  (total 48 KB)

    const int tid  = threadIdx.x;
    const int lane = tid & 31;
    const int wid  = tid >> 5;
    const int wm   = (wid & 3) * 32;   // warp row offset within 128
    const int wn   = (wid >> 2) * 64;  // warp col offset within 128
    const int bn0  = blockIdx.x * 128;
    const size_t Abase = (size_t)blockIdx.y * 128 * K_DIM;

    const uint32_t sA_u = (uint32_t)__cvta_generic_to_shared(&sA[0][0]);
    const uint32_t sB_u = (uint32_t)__cvta_generic_to_shared(&sB[0][0]);

    auto loadTiles = [&](int stage, int kt) {
        // A tile: 128 rows x 4 chunks(16B). swizzle: chunk ^= (row>>1)&3
        #pragma unroll
        for (int j = 0; j < 2; j++) {
            int id = tid + j * 256;
            int r  = id >> 2, c = id & 3;
            const __nv_bfloat16* src = g_Abf + Abase + (size_t)r * K_DIM + kt * 32 + c * 8;
            int swc = c ^ ((r >> 1) & 3);
            cp_async16(sA_u + (uint32_t)((stage * 4096 + r * 32 + swc * 8) * 2), src);
        }
        // B tile: 32 rows x 16 chunks(16B). swizzle: chunk ^= row&7
        #pragma unroll
        for (int j = 0; j < 2; j++) {
            int id = tid + j * 256;
            int k  = id >> 4, c = id & 15;
            const __nv_bfloat16* src = g_Wbf + (size_t)(kt * 32 + k) * N_DIM + bn0 + c * 8;
            int swc = c ^ (k & 7);
            cp_async16(sB_u + (uint32_t)((stage * 4096 + k * 128 + swc * 8) * 2), src);
        }
        asm volatile("cp.async.commit_group;\n");
    };

    float acc[2][8][4];
    #pragma unroll
    for (int mf = 0; mf < 2; mf++)
        #pragma unroll
        for (int nf = 0; nf < 8; nf++)
            #pragma unroll
            for (int i = 0; i < 4; i++) acc[mf][nf][i] = 0.f;

    loadTiles(0, 0);
    loadTiles(1, 1);

    int cur = 0, nxt = 2;
    for (int kt = 0; kt < KTILES; kt++) {
        if (kt < KTILES - 1) asm volatile("cp.async.wait_group 1;\n");
        else                 asm volatile("cp.async.wait_group 0;\n");
        __syncthreads();
        if (kt + 2 < KTILES) loadTiles(nxt, kt + 2);

        #pragma unroll
        for (int kk = 0; kk < 2; kk++) {
            uint32_t afr[2][4], bfr[16];
            #pragma unroll
            for (int mf = 0; mf < 2; mf++) {
                int r   = wm + mf * 16 + (lane & 15);
                int ch  = kk * 2 + (lane >> 4);
                int swc = ch ^ ((r >> 1) & 3);
                ldm_x4(afr[mf][0], afr[mf][1], afr[mf][2], afr[mf][3],
                       sA_u + (uint32_t)((cur * 4096 + r * 32 + swc * 8) * 2));
            }
            #pragma unroll
            for (int nq = 0; nq < 4; nq++) {
                int k   = kk * 16 + (lane & 15);
                int ch  = (wn >> 3) + nq * 2 + (lane >> 4);
                int swc = ch ^ (k & 7);
                ldm_x4_t(bfr[nq * 4 + 0], bfr[nq * 4 + 1], bfr[nq * 4 + 2], bfr[nq * 4 + 3],
                         sB_u + (uint32_t)((cur * 4096 + k * 128 + swc * 8) * 2));
            }
            #pragma unroll
            for (int mf = 0; mf < 2; mf++)
                #pragma unroll
                for (int nf = 0; nf < 8; nf++)
                    mma_bf16(acc[mf][nf], afr[mf], bfr[2 * nf], bfr[2 * nf + 1]);
        }
        cur = (cur + 1) % STAGES;
        nxt = (nxt + 1) % STAGES;
    }

    // Epilogue: add bias (L1/L2-cached float2 loads), convert to bf16, store feats
    const int g = lane >> 2, t4 = lane & 3;
    #pragma unroll
    for (int mf = 0; mf < 2; mf++) {
        size_t row0 = (size_t)blockIdx.y * 128 + wm + mf * 16 + g;
        #pragma unroll
        for (int nf = 0; nf < 8; nf++) {
            int col   = wn + nf * 8 + t4 * 2;
            float2 bb = __ldg((const float2*)(bias + bn0 + col));
            __nv_bfloat162 v0 = __floats2bfloat162_rn(acc[mf][nf][0] + bb.x, acc[mf][nf][1] + bb.y);
            __nv_bfloat162 v1 = __floats2bfloat162_rn(acc[mf][nf][2] + bb.x, acc[mf][nf][3] + bb.y);
            *(__nv_bfloat162*)(g_feats + row0 * N_DIM + bn0 + col)       = v0;
            *(__nv_bfloat162*)(g_feats + (row0 + 8) * N_DIM + bn0 + col) = v1;
        }
    }
}

// ---------------------------------------------------------------------------
// Per-batch kernel: Gram (14x14) via warp-per-row, norms, weighting, softmax.
// One block per batch, 448 threads = 14 warps.
// ---------------------------------------------------------------------------
__global__ __launch_bounds__(448) void batch_kernel(const float* __restrict__ area,
                                                    const float* __restrict__ co,
                                                    float* __restrict__ out) {
    __shared__ float Fs[14][772];    // stride 772 breaks 768-stride bank aliasing
    __shared__ float G[14][16];      // padded
    __shared__ float s_area[14];
    __shared__ float s_rnorm[14];
    __shared__ float s_scal[2];      // [0] = 1/(cwsum+eps), [1] = 1/(amax^2+eps)

    const int b = blockIdx.x, tid = threadIdx.x;
    const int wid = tid >> 5, lane = tid & 31;

    // Stage feats (14 x 768 bf16 -> fp32 smem), float4 stores
    const __nv_bfloat16* fb = g_feats + (size_t)b * NREG * DDIM;
    for (int idx = tid; idx < NREG * 96; idx += 448) {
        int n = idx / 96, c = idx - n * 96;
        uint4 raw = *(const uint4*)(fb + n * DDIM + c * 8);
        const __nv_bfloat162* h = (const __nv_bfloat162*)&raw;
        float2 f0 = __bfloat1622float2(h[0]);
        float2 f1 = __bfloat1622float2(h[1]);
        float2 f2 = __bfloat1622float2(h[2]);
        float2 f3 = __bfloat1622float2(h[3]);
        float4* dstp = (float4*)&Fs[n][c * 8];
        dstp[0] = make_float4(f0.x, f0.y, f1.x, f1.y);
        dstp[1] = make_float4(f2.x, f2.y, f3.x, f3.y);
    }
    if (tid < NREG) s_area[tid] = area[b * NREG + tid];
    if (tid == 14) {  // deterministic cw sum (exact fp32 serial)
        float s = 0.f;
        for (int i = 0; i < NREG * NREG; i++) s += co[i];
        s_scal[0] = 1.0f / (s + 1e-8f);
    }
    if (tid == 15) {  // max(aw) == (max a)^2 since a >= 0
        float am = 0.f;
        for (int i = 0; i < NREG; i++) am = fmaxf(am, area[b * NREG + i]);
        s_scal[1] = 1.0f / (am * am + 1e-8f);
    }
    __syncthreads();

    // Gram: warp `wid` computes row wid. Row cached in registers, conflict-free LDS.
    {
        float rreg[24];
        #pragma unroll
        for (int j = 0; j < 24; j++) rreg[j] = Fs[wid][lane + 32 * j];
        #pragma unroll 2
        for (int m = 0; m < NREG; m++) {
            float acc = 0.f;
            #pragma unroll
            for (int j = 0; j < 24; j++) acc += rreg[j] * Fs[m][lane + 32 * j];
            #pragma unroll
            for (int off = 16; off > 0; off >>= 1)
                acc += __shfl_xor_sync(0xFFFFFFFFu, acc, off);
            if (lane == 0) G[wid][m] = acc;
        }
    }
    __syncthreads();

    if (tid < NREG) {
        float nn = sqrtf(G[tid][tid]);
        s_rnorm[tid] = 1.0f / fmaxf(nn, 1e-12f);
    }
    __syncthreads();

    if (tid < NREG) {
        const int n = tid;
        float vals[NREG];
        const float an = s_area[n], rn = s_rnorm[n];
        const float inv_cw = s_scal[0], inv_aw = s_scal[1];
        float mx = -1e30f;
        #pragma unroll
        for (int m = 0; m < NREG; m++) {
            float sim = G[n][m] * rn * s_rnorm[m];
            float aw  = an * s_area[m] * inv_aw;
            float cwv = co[n * NREG + m] * inv_cw;
            float v   = sim * aw * cwv;
            vals[m] = v;
            mx = fmaxf(mx, v);
        }
        float sum = 0.f;
        #pragma unroll
        for (int m = 0; m < NREG; m++) { vals[m] = expf(vals[m] - mx); sum += vals[m]; }
        float inv = 1.0f / sum;
        float* op = out + ((size_t)b * NREG * NREG + n * NREG);
        #pragma unroll
        for (int m = 0; m < NREG; m++) op[m] = vals[m] * inv;
    }
}

// ---------------------------------------------------------------------------
// kernel_launch
// Inputs (metadata order): region_features [8192,14,768] f32, area_matrix
// [8192,14] f32, co_occurrence_count [14,14] f32, W [768,768] f32, b [768] f32.
// Output: [8192,14,14] f32.
// ---------------------------------------------------------------------------
extern "C" void kernel_launch(void* const* d_in, const int* in_sizes, int n_in,
                              void* d_out, int out_size) {
    const float* X    = (const float*)d_in[0];
    const float* area = (const float*)d_in[1];
    const float* co   = (const float*)d_in[2];
    const float* W    = (const float*)d_in[3];
    const float* bias = (const float*)d_in[4];
    float* out        = (float*)d_out;

    cvtA_kernel<<<(M_TOTAL * (size_t)K_DIM) / 2048, 256>>>(X);   // 43008 blocks
    cvtW_kernel<<<((size_t)K_DIM * N_DIM) / 2048, 256>>>(W);     // 288 blocks
    gemm_kernel<<<dim3(N_DIM / 128, M_TOTAL / 128), 256>>>(bias);
    batch_kernel<<<BATCH, 448>>>(area, co, out);
}